// round 13
// baseline (speedup 1.0000x reference)
#include <cuda_runtime.h>
#include <cuda_bf16.h>
#include <cstdint>

#define NFE 256
#define NFC 128
#define MAXN 50000
#define MAXE 800000
#define NPAD 50176   // padded row count for tail-safe cp.async

// Scratch buffers
__device__ float g_Y1[(size_t)MAXN * 256];
__device__ float g_Y2[(size_t)MAXN * 256];
// packed bf16 hi/lo planes of H1 halves (mma-ready: word w = bf16x2(h[2w],h[2w+1]))
__device__ uint32_t g_AeHi[(size_t)NPAD * 64];
__device__ uint32_t g_AeLo[(size_t)NPAD * 64];
__device__ uint32_t g_AcHi[(size_t)NPAD * 64];
__device__ uint32_t g_AcLo[(size_t)NPAD * 64];
__device__ int g_cnt[MAXN];
__device__ int g_fill[MAXN];
__device__ int g_rowptr[MAXN + 1];
__device__ int g_csrc[MAXE];

__device__ __forceinline__ float lrelu(float v) { return v > 0.f ? v : 0.2f * v; }

// split two floats into bf16x2 hi word + bf16x2 lo word
__device__ __forceinline__ void split2(float x, float y, uint32_t& hi, uint32_t& lo) {
    __nv_bfloat162 h = __float22bfloat162_rn(make_float2(x, y));
    hi = *reinterpret_cast<uint32_t*>(&h);
    float rx = x - __bfloat162float(h.x);
    float ry = y - __bfloat162float(h.y);
    __nv_bfloat162 l = __float22bfloat162_rn(make_float2(rx, ry));
    lo = *reinterpret_cast<uint32_t*>(&l);
}

// ---------------- CSR build ----------------
__global__ void zero_cnt_kernel(int n) {
    int i = blockIdx.x * blockDim.x + threadIdx.x;
    if (i < n) g_cnt[i] = 0;
}

__global__ void hist_kernel(const int* __restrict__ ei, int E) {
    int e = blockIdx.x * blockDim.x + threadIdx.x;
    if (e < E) atomicAdd(&g_cnt[ei[E + e]], 1);
}

__global__ __launch_bounds__(1024) void scan_kernel(int N) {
    __shared__ int ssum[1024];
    int tid = threadIdx.x;
    int chunk = (N + 1023) / 1024;
    int lo = tid * chunk;
    int hi = lo + chunk;
    if (hi > N) hi = N;
    int s = 0;
    for (int i = lo; i < hi; i++) s += g_cnt[i];
    ssum[tid] = s;
    __syncthreads();
    for (int off = 1; off < 1024; off <<= 1) {
        int t = (tid >= off) ? ssum[tid - off] : 0;
        __syncthreads();
        ssum[tid] += t;
        __syncthreads();
    }
    int run = ssum[tid] - s;
    for (int i = lo; i < hi; i++) {
        g_rowptr[i] = run;
        g_fill[i] = run;
        run += g_cnt[i];
    }
    if (tid == 1023) g_rowptr[N] = ssum[1023];
}

__global__ void fill_kernel(const int* __restrict__ ei, int E) {
    int e = blockIdx.x * blockDim.x + threadIdx.x;
    if (e < E) {
        int s = ei[e];
        int d = ei[E + e];
        int pos = atomicAdd(&g_fill[d], 1);
        g_csrc[pos] = s;
    }
}

#define MMA_BF16(D, Areg, B0, B1)                                            \
    asm volatile("mma.sync.aligned.m16n8k16.row.col.f32.bf16.bf16.f32 "      \
                 "{%0,%1,%2,%3},{%4,%5,%6,%7},{%8,%9},{%0,%1,%2,%3};"        \
                 : "+f"(D[0]), "+f"(D[1]), "+f"(D[2]), "+f"(D[3])            \
                 : "r"(Areg[0]), "r"(Areg[1]), "r"(Areg[2]), "r"(Areg[3]),   \
                   "r"(B0), "r"(B1))

// ---------------- Layer-1 BF16x3 GEMM (fp32 input, in-loop split, depth-2 lookahead) ----------------
__global__ __launch_bounds__(256, 2) void gemm_bf16_kernel(
    const float* __restrict__ A, const float* __restrict__ me,
    const float* __restrict__ B, float* __restrict__ Y,
    int M, int K, int lda, int mode)
{
    __shared__ uint32_t Ahi[128][12], Alo[128][12];
    __shared__ uint32_t Bhi[8][132], Blo[8][132];

    const int tid = threadIdx.x;
    const int lane = tid & 31;
    const int warp = tid >> 5;
    const int wr = warp & 1;
    const int wc = warp >> 1;
    const int rowBase = blockIdx.x * 128;

    float d[4][4][4];
#pragma unroll
    for (int m = 0; m < 4; m++)
#pragma unroll
        for (int n = 0; n < 4; n++)
#pragma unroll
            for (int r = 0; r < 4; r++) d[m][n][r] = 0.f;

    const int a_row = tid >> 2;
    const int a_kq = (tid & 3) << 2;
    const int b_kp = tid >> 5;
    const int b_c4 = lane << 2;

    float4 pa[2][2], pbe[2], pbo[2];

    auto prefetch = [&](int k0, int buf) {
#pragma unroll
        for (int it = 0; it < 2; it++) {
            int grow = rowBase + a_row + it * 64;
            float4 v = make_float4(0.f, 0.f, 0.f, 0.f);
            if (grow < M) {
                v = *(const float4*)(A + (size_t)grow * lda + k0 + a_kq);
                if (mode == 0) {
                    if (v.x == 0.f) v.x = me[k0 + a_kq + 0];
                    if (v.y == 0.f) v.y = me[k0 + a_kq + 1];
                    if (v.z == 0.f) v.z = me[k0 + a_kq + 2];
                    if (v.w == 0.f) v.w = me[k0 + a_kq + 3];
                }
            }
            pa[buf][it] = v;
        }
        pbe[buf] = *(const float4*)(B + (size_t)(k0 + 2 * b_kp) * 128 + b_c4);
        pbo[buf] = *(const float4*)(B + (size_t)(k0 + 2 * b_kp + 1) * 128 + b_c4);
    };

    auto split_store = [&](int buf) {
        const int kp0 = (tid & 3) << 1;
#pragma unroll
        for (int it = 0; it < 2; it++) {
            int rr = a_row + it * 64;
            uint32_t h0, l0, h1, l1;
            split2(pa[buf][it].x, pa[buf][it].y, h0, l0);
            split2(pa[buf][it].z, pa[buf][it].w, h1, l1);
            Ahi[rr][kp0] = h0; Ahi[rr][kp0 + 1] = h1;
            Alo[rr][kp0] = l0; Alo[rr][kp0 + 1] = l1;
        }
        float ev[4] = {pbe[buf].x, pbe[buf].y, pbe[buf].z, pbe[buf].w};
        float od[4] = {pbo[buf].x, pbo[buf].y, pbo[buf].z, pbo[buf].w};
#pragma unroll
        for (int i = 0; i < 4; i++) {
            uint32_t h, l;
            split2(ev[i], od[i], h, l);
            Bhi[b_kp][b_c4 + i] = h;
            Blo[b_kp][b_c4 + i] = l;
        }
    };

    const int nC = K >> 4;
    prefetch(0, 0);
    if (nC > 1) prefetch(16, 1);

#pragma unroll 1
    for (int chunk = 0; chunk < nC; chunk++) {
        const int buf = chunk & 1;
        split_store(buf);
        __syncthreads();
        if (chunk + 2 < nC) prefetch((chunk + 2) << 4, buf);

        uint32_t ah[4][4], al[4][4];
        const int kp = lane & 3;
#pragma unroll
        for (int m = 0; m < 4; m++) {
            int r0 = wr * 64 + m * 16 + (lane >> 2);
            ah[m][0] = Ahi[r0][kp];
            ah[m][1] = Ahi[r0 + 8][kp];
            ah[m][2] = Ahi[r0][kp + 4];
            ah[m][3] = Ahi[r0 + 8][kp + 4];
            al[m][0] = Alo[r0][kp];
            al[m][1] = Alo[r0 + 8][kp];
            al[m][2] = Alo[r0][kp + 4];
            al[m][3] = Alo[r0 + 8][kp + 4];
        }
#pragma unroll
        for (int n = 0; n < 4; n++) {
            int cb = wc * 32 + n * 8 + (lane >> 2);
            uint32_t bh0 = Bhi[kp][cb], bh1 = Bhi[kp + 4][cb];
            uint32_t bl0 = Blo[kp][cb], bl1 = Blo[kp + 4][cb];
#pragma unroll
            for (int m = 0; m < 4; m++) {
                MMA_BF16(d[m][n], ah[m], bh0, bh1);
                MMA_BF16(d[m][n], al[m], bh0, bh1);
                MMA_BF16(d[m][n], ah[m], bl0, bl1);
            }
        }
        __syncthreads();
    }

#pragma unroll
    for (int m = 0; m < 4; m++) {
        int r = rowBase + wr * 64 + m * 16 + (lane >> 2);
#pragma unroll
        for (int n = 0; n < 4; n++) {
            int cc = wc * 32 + n * 8 + ((lane & 3) << 1);
            if (r < M)
                *(float2*)(Y + (size_t)r * 256 + cc) = make_float2(d[m][n][0], d[m][n][1]);
            if (r + 8 < M)
                *(float2*)(Y + (size_t)(r + 8) * 256 + cc) = make_float2(d[m][n][2], d[m][n][3]);
        }
    }
}

// ---------------- Layer-2 GEMM: packed A via cp.async, B streamed per chunk ----------------
__global__ __launch_bounds__(256, 2) void gemm_l2b_kernel(
    const uint32_t* __restrict__ aHi, const uint32_t* __restrict__ aLo,
    const float* __restrict__ B, float* __restrict__ Y, int M)
{
    __shared__ uint32_t sAhi[2][128][12], sAlo[2][128][12];
    __shared__ uint32_t Bhi[8][132], Blo[8][132];

    const int tid = threadIdx.x;
    const int lane = tid & 31;
    const int warp = tid >> 5;
    const int wr = warp & 1;
    const int wc = warp >> 1;
    const int rowBase = blockIdx.x * 128;

    float d[4][4][4];
#pragma unroll
    for (int m = 0; m < 4; m++)
#pragma unroll
        for (int n = 0; n < 4; n++)
#pragma unroll
            for (int r = 0; r < 4; r++) d[m][n][r] = 0.f;

    const int c_row = tid >> 1;
    const int c_half = tid & 1;
    const uint32_t* srcHi = aHi + (size_t)(rowBase + c_row) * 64 + c_half * 4;
    const uint32_t* srcLo = aLo + (size_t)(rowBase + c_row) * 64 + c_half * 4;

    auto issueA = [&](int chunk) {
        int stage = chunk & 1;
        uint32_t dh = (uint32_t)__cvta_generic_to_shared(&sAhi[stage][c_row][c_half * 4]);
        uint32_t dl = (uint32_t)__cvta_generic_to_shared(&sAlo[stage][c_row][c_half * 4]);
        asm volatile("cp.async.cg.shared.global [%0], [%1], 16;" :: "r"(dh), "l"(srcHi + chunk * 8));
        asm volatile("cp.async.cg.shared.global [%0], [%1], 16;" :: "r"(dl), "l"(srcLo + chunk * 8));
        asm volatile("cp.async.commit_group;");
    };

    const int b_kp = tid >> 5;
    const int b_c4 = lane << 2;
    float4 pbe, pbo;

    auto prefetchB = [&](int k0) {
        pbe = *(const float4*)(B + (size_t)(k0 + 2 * b_kp) * 128 + b_c4);
        pbo = *(const float4*)(B + (size_t)(k0 + 2 * b_kp + 1) * 128 + b_c4);
    };

    auto storeB = [&]() {
        float ev[4] = {pbe.x, pbe.y, pbe.z, pbe.w};
        float od[4] = {pbo.x, pbo.y, pbo.z, pbo.w};
#pragma unroll
        for (int i = 0; i < 4; i++) {
            uint32_t h, l;
            split2(ev[i], od[i], h, l);
            Bhi[b_kp][b_c4 + i] = h;
            Blo[b_kp][b_c4 + i] = l;
        }
    };

    issueA(0);
    issueA(1);
    prefetchB(0);

    const int kp = lane & 3;
#pragma unroll 1
    for (int chunk = 0; chunk < 8; chunk++) {
        storeB();
        if (chunk < 6) asm volatile("cp.async.wait_group 1;");
        else           asm volatile("cp.async.wait_group 0;");
        __syncthreads();
        if (chunk + 1 < 8) prefetchB((chunk + 1) * 16);

        const uint32_t (*Ah)[12] = sAhi[chunk & 1];
        const uint32_t (*Al)[12] = sAlo[chunk & 1];

        uint32_t ah[4][4], al[4][4];
#pragma unroll
        for (int m = 0; m < 4; m++) {
            int r0 = wr * 64 + m * 16 + (lane >> 2);
            ah[m][0] = Ah[r0][kp];
            ah[m][1] = Ah[r0 + 8][kp];
            ah[m][2] = Ah[r0][kp + 4];
            ah[m][3] = Ah[r0 + 8][kp + 4];
            al[m][0] = Al[r0][kp];
            al[m][1] = Al[r0 + 8][kp];
            al[m][2] = Al[r0][kp + 4];
            al[m][3] = Al[r0 + 8][kp + 4];
        }
#pragma unroll
        for (int n = 0; n < 4; n++) {
            int cb = wc * 32 + n * 8 + (lane >> 2);
            uint32_t bh0 = Bhi[kp][cb], bh1 = Bhi[kp + 4][cb];
            uint32_t bl0 = Blo[kp][cb], bl1 = Blo[kp + 4][cb];
#pragma unroll
            for (int m = 0; m < 4; m++) {
                MMA_BF16(d[m][n], ah[m], bh0, bh1);
                MMA_BF16(d[m][n], al[m], bh0, bh1);
                MMA_BF16(d[m][n], ah[m], bl0, bl1);
            }
        }
        __syncthreads();
        if (chunk + 2 < 8) issueA(chunk + 2);
    }

#pragma unroll
    for (int m = 0; m < 4; m++) {
        int r = rowBase + wr * 64 + m * 16 + (lane >> 2);
#pragma unroll
        for (int n = 0; n < 4; n++) {
            int cc = wc * 32 + n * 8 + ((lane & 3) << 1);
            if (r < M)
                *(float2*)(Y + (size_t)r * 256 + cc) = make_float2(d[m][n][0], d[m][n][1]);
            if (r + 8 < M)
                *(float2*)(Y + (size_t)(r + 8) * 256 + cc) = make_float2(d[m][n][2], d[m][n][3]);
        }
    }
}

// ---------------- gather core (warp-per-node neighbor sum) ----------------
__device__ __forceinline__ void gather_row(const float* __restrict__ Y, int gwarp,
                                           int lane, int j0, float* acc)
{
    const unsigned FULL = 0xffffffffu;
    int beg = g_rowptr[gwarp];
    int end = g_rowptr[gwarp + 1];
#pragma unroll
    for (int i = 0; i < 8; i++) acc[i] = 0.f;

    for (int base = beg; base < end; base += 32) {
        int idx = base + lane;
        int sl = (idx < end) ? g_csrc[idx] : 0;
        int cnt = end - base;
        if (cnt > 32) cnt = 32;
        int j = 0;
        for (; j + 3 < cnt; j += 4) {
            int s0 = __shfl_sync(FULL, sl, j);
            int s1 = __shfl_sync(FULL, sl, j + 1);
            int s2 = __shfl_sync(FULL, sl, j + 2);
            int s3 = __shfl_sync(FULL, sl, j + 3);
            const float* p0 = Y + (size_t)s0 * 256 + j0;
            const float* p1 = Y + (size_t)s1 * 256 + j0;
            const float* p2 = Y + (size_t)s2 * 256 + j0;
            const float* p3 = Y + (size_t)s3 * 256 + j0;
            float4 a0 = *(const float4*)p0;
            float4 a1 = *(const float4*)(p0 + 4);
            float4 b0 = *(const float4*)p1;
            float4 b1 = *(const float4*)(p1 + 4);
            float4 c0 = *(const float4*)p2;
            float4 c1 = *(const float4*)(p2 + 4);
            float4 e0 = *(const float4*)p3;
            float4 e1 = *(const float4*)(p3 + 4);
            acc[0] += (a0.x + b0.x) + (c0.x + e0.x);
            acc[1] += (a0.y + b0.y) + (c0.y + e0.y);
            acc[2] += (a0.z + b0.z) + (c0.z + e0.z);
            acc[3] += (a0.w + b0.w) + (c0.w + e0.w);
            acc[4] += (a1.x + b1.x) + (c1.x + e1.x);
            acc[5] += (a1.y + b1.y) + (c1.y + e1.y);
            acc[6] += (a1.z + b1.z) + (c1.z + e1.z);
            acc[7] += (a1.w + b1.w) + (c1.w + e1.w);
        }
        for (; j < cnt; j++) {
            int s0 = __shfl_sync(FULL, sl, j);
            const float* p0 = Y + (size_t)s0 * 256 + j0;
            float4 a0 = *(const float4*)p0;
            float4 a1 = *(const float4*)(p0 + 4);
            acc[0] += a0.x; acc[1] += a0.y; acc[2] += a0.z; acc[3] += a0.w;
            acc[4] += a1.x; acc[5] += a1.y; acc[6] += a1.z; acc[7] += a1.w;
        }
    }
}

__device__ __forceinline__ void gin_epilogue(const float* __restrict__ Y, int gwarp, int j0,
                                             const float* bb, float fac,
                                             const float* acc, float* h)
{
    const float* py = Y + (size_t)gwarp * 256 + j0;
    float4 y0 = *(const float4*)py;
    float4 y1 = *(const float4*)(py + 4);
    h[0] = lrelu(fmaf(y0.x, fac, acc[0]) + bb[0]);
    h[1] = lrelu(fmaf(y0.y, fac, acc[1]) + bb[1]);
    h[2] = lrelu(fmaf(y0.z, fac, acc[2]) + bb[2]);
    h[3] = lrelu(fmaf(y0.w, fac, acc[3]) + bb[3]);
    h[4] = lrelu(fmaf(y1.x, fac, acc[4]) + bb[4]);
    h[5] = lrelu(fmaf(y1.y, fac, acc[5]) + bb[5]);
    h[6] = lrelu(fmaf(y1.z, fac, acc[6]) + bb[6]);
    h[7] = lrelu(fmaf(y1.w, fac, acc[7]) + bb[7]);
}

// gather-1: writes packed bf16 hi/lo planes (mma-ready for layer-2 GEMM)
__global__ __launch_bounds__(256) void gather1_kernel(
    const float* __restrict__ Y,
    const float* __restrict__ be, const float* __restrict__ bc,
    const float* __restrict__ epe, const float* __restrict__ epc, int Nn)
{
    int gwarp = (blockIdx.x * 256 + threadIdx.x) >> 5;
    int lane = threadIdx.x & 31;
    if (gwarp >= Nn) return;
    int j0 = lane * 8;

    float acc[8];
    gather_row(Y, gwarp, lane, j0, acc);

    float fac;
    const float* bb;
    if (j0 < 128) { fac = 2.f + *epe; bb = be + j0; }
    else          { fac = 2.f + *epc; bb = bc + (j0 - 128); }

    float h[8];
    gin_epilogue(Y, gwarp, j0, bb, fac, acc, h);

    uint32_t hi[4], lo[4];
    split2(h[0], h[1], hi[0], lo[0]);
    split2(h[2], h[3], hi[1], lo[1]);
    split2(h[4], h[5], hi[2], lo[2]);
    split2(h[6], h[7], hi[3], lo[3]);

    if (lane < 16) {
        size_t off = (size_t)gwarp * 64 + lane * 4;
        *(uint4*)(g_AeHi + off) = make_uint4(hi[0], hi[1], hi[2], hi[3]);
        *(uint4*)(g_AeLo + off) = make_uint4(lo[0], lo[1], lo[2], lo[3]);
    } else {
        size_t off = (size_t)gwarp * 64 + (lane - 16) * 4;
        *(uint4*)(g_AcHi + off) = make_uint4(hi[0], hi[1], hi[2], hi[3]);
        *(uint4*)(g_AcLo + off) = make_uint4(lo[0], lo[1], lo[2], lo[3]);
    }
}

// gather-2: fused output head: out = lrelu(H2 @ Wm + bm)
__global__ __launch_bounds__(256) void gather2_kernel(
    const float* __restrict__ Y,
    const float* __restrict__ be, const float* __restrict__ bc,
    const float* __restrict__ epe, const float* __restrict__ epc,
    const float* __restrict__ Wm, const float* __restrict__ bm,
    float* __restrict__ out, int Nn)
{
    __shared__ float sW[2048];
    __shared__ float sb[8];
    for (int i = threadIdx.x; i < 2048; i += 256) sW[i] = Wm[i];
    if (threadIdx.x < 8) sb[threadIdx.x] = bm[threadIdx.x];
    __syncthreads();

    int gwarp = (blockIdx.x * 256 + threadIdx.x) >> 5;
    int lane = threadIdx.x & 31;
    if (gwarp >= Nn) return;
    int j0 = lane * 8;

    float acc[8];
    gather_row(Y, gwarp, lane, j0, acc);

    float fac;
    const float* bb;
    if (j0 < 128) { fac = 2.f + *epe; bb = be + j0; }
    else          { fac = 2.f + *epc; bb = bc + (j0 - 128); }

    float h[8];
    gin_epilogue(Y, gwarp, j0, bb, fac, acc, h);

    float o[8];
#pragma unroll
    for (int n = 0; n < 8; n++) o[n] = 0.f;
#pragma unroll
    for (int jj = 0; jj < 8; jj++) {
        const float* w = &sW[(size_t)(j0 + jj) * 8];
#pragma unroll
        for (int n = 0; n < 8; n++) o[n] += h[jj] * w[n];
    }
#pragma unroll
    for (int off = 16; off >= 1; off >>= 1)
#pragma unroll
        for (int n = 0; n < 8; n++)
            o[n] += __shfl_xor_sync(0xffffffffu, o[n], off);
    if (lane == 0) {
#pragma unroll
        for (int n = 0; n < 8; n++)
            out[(size_t)gwarp * 8 + n] = lrelu(o[n] + sb[n]);
    }
}

// ---------------- central MLP ----------------
__global__ __launch_bounds__(256) void central_kernel(
    const float* __restrict__ out, const int* __restrict__ cidx,
    const float* __restrict__ Wp1, const float* __restrict__ bp1,
    const float* __restrict__ Wp2, const float* __restrict__ bp2,
    float* __restrict__ logits, int C)
{
    __shared__ float s1[1024];
    __shared__ float sb1[128];
    __shared__ float s2[1024];
    __shared__ float sb2[8];
    for (int i = threadIdx.x; i < 1024; i += 256) { s1[i] = Wp1[i]; s2[i] = Wp2[i]; }
    if (threadIdx.x < 128) sb1[threadIdx.x] = bp1[threadIdx.x];
    if (threadIdx.x < 8) sb2[threadIdx.x] = bp2[threadIdx.x];
    __syncthreads();

    int t = blockIdx.x * 256 + threadIdx.x;
    if (t >= C) return;
    int ci = cidx[t];
    float g[8];
#pragma unroll
    for (int k = 0; k < 8; k++) g[k] = out[(size_t)ci * 8 + k];
    float acc[8];
#pragma unroll
    for (int m = 0; m < 8; m++) acc[m] = sb2[m];
    for (int n = 0; n < 128; n++) {
        float tn = sb1[n];
#pragma unroll
        for (int k = 0; k < 8; k++) tn += g[k] * s1[k * 128 + n];
        tn = fmaxf(tn, 0.f);
#pragma unroll
        for (int m = 0; m < 8; m++) acc[m] += tn * s2[n * 8 + m];
    }
#pragma unroll
    for (int m = 0; m < 8; m++) logits[(size_t)t * 8 + m] = acc[m];
}

extern "C" void kernel_launch(void* const* d_in, const int* in_sizes, int n_in,
                              void* d_out, int out_size)
{
    const float* x    = (const float*)d_in[0];
    const float* c    = (const float*)d_in[1];
    const int*   ei   = (const int*)d_in[2];
    const int*   cidx = (const int*)d_in[3];
    const float* me_x = (const float*)d_in[4];
    const float* me_c = (const float*)d_in[5];
    const float* W1e  = (const float*)d_in[6];
    const float* b1e  = (const float*)d_in[7];
    const float* e1e  = (const float*)d_in[8];
    const float* W2e  = (const float*)d_in[9];
    const float* b2e  = (const float*)d_in[10];
    const float* e2e  = (const float*)d_in[11];
    const float* W1c  = (const float*)d_in[12];
    const float* b1c  = (const float*)d_in[13];
    const float* e1c  = (const float*)d_in[14];
    const float* W2c  = (const float*)d_in[15];
    const float* b2c  = (const float*)d_in[16];
    const float* e2c  = (const float*)d_in[17];
    const float* Wm   = (const float*)d_in[18];
    const float* bm   = (const float*)d_in[19];
    const float* Wp1  = (const float*)d_in[20];
    const float* bp1  = (const float*)d_in[21];
    const float* Wp2  = (const float*)d_in[22];
    const float* bp2  = (const float*)d_in[23];

    const int Nn = in_sizes[0] / NFE;       // 50000
    const int E  = in_sizes[2] / 2;         // 800000
    const int C  = in_sizes[3];             // 512

    float *Y1, *Y2;
    uint32_t *AeHi, *AeLo, *AcHi, *AcLo;
    cudaGetSymbolAddress((void**)&Y1, g_Y1);
    cudaGetSymbolAddress((void**)&Y2, g_Y2);
    cudaGetSymbolAddress((void**)&AeHi, g_AeHi);
    cudaGetSymbolAddress((void**)&AeLo, g_AeLo);
    cudaGetSymbolAddress((void**)&AcHi, g_AcHi);
    cudaGetSymbolAddress((void**)&AcLo, g_AcLo);

    float* out_p    = (float*)d_out;              // [N, 8]
    float* logits_p = (float*)d_out + (size_t)Nn * 8;

    // Fork-join stream overlap. Stream/events created fresh each call and
    // intentionally not destroyed (destroy during capture would break the graph).
    cudaStream_t s1;
    cudaEvent_t evFork, evJoin, evFork2, evJoin2;
    cudaStreamCreateWithFlags(&s1, cudaStreamNonBlocking);
    cudaEventCreateWithFlags(&evFork, cudaEventDisableTiming);
    cudaEventCreateWithFlags(&evJoin, cudaEventDisableTiming);
    cudaEventCreateWithFlags(&evFork2, cudaEventDisableTiming);
    cudaEventCreateWithFlags(&evJoin2, cudaEventDisableTiming);

    cudaEventRecord(evFork, 0);
    cudaStreamWaitEvent(s1, evFork, 0);

    // CSR build (by dst) on s1 — hidden under the layer-1 GEMMs
    zero_cnt_kernel<<<(Nn + 255) / 256, 256, 0, s1>>>(Nn);
    hist_kernel<<<(E + 255) / 256, 256, 0, s1>>>(ei, E);
    scan_kernel<<<1, 1024, 0, s1>>>(Nn);
    fill_kernel<<<(E + 255) / 256, 256, 0, s1>>>(ei, E);
    cudaEventRecord(evJoin, s1);

    int gridM = (Nn + 127) / 128;
    int gridW = (Nn * 32 + 255) / 256;

    // layer-1 projections (matmul-first) on main stream, concurrent with CSR build
    gemm_bf16_kernel<<<gridM, 256>>>(x, me_x, W1e, Y1, Nn, NFE, NFE, 0);
    gemm_bf16_kernel<<<gridM, 256>>>(c, me_c, W1c, Y1 + 128, Nn, NFC, NFC, 0);

    // Join: gather1 needs both CSR and Y1
    cudaStreamWaitEvent(0, evJoin, 0);

    // layer-1 aggregation + epilogue -> packed H1
    gather1_kernel<<<gridW, 256>>>(Y1, b1e, b1c, e1e, e1c, Nn);

    // layer-2 projections: Ae on main, Ac on side stream (tail-wave packing)
    cudaEventRecord(evFork2, 0);
    cudaStreamWaitEvent(s1, evFork2, 0);
    gemm_l2b_kernel<<<gridM, 256, 0, s1>>>(AcHi, AcLo, W2c, Y2 + 128, Nn);
    cudaEventRecord(evJoin2, s1);
    gemm_l2b_kernel<<<gridM, 256>>>(AeHi, AeLo, W2e, Y2, Nn);
    cudaStreamWaitEvent(0, evJoin2, 0);

    // layer-2 aggregation + fused output head
    gather2_kernel<<<gridW, 256>>>(Y2, b2e, b2c, e2e, e2c, Wm, bm, out_p, Nn);

    // central MLP
    central_kernel<<<(C + 255) / 256, 256>>>(out_p, cidx, Wp1, bp1, Wp2, bp2, logits_p, C);
}

// round 14
// speedup vs baseline: 1.6415x; 1.6415x over previous
#include <cuda_runtime.h>
#include <cuda_bf16.h>
#include <cstdint>

#define NFE 256
#define NFC 128
#define MAXN 50000
#define MAXE 800000
#define NPAD 50176   // padded row count for tail-safe cp.async

// Scratch buffers
__device__ float g_Y1[(size_t)MAXN * 256];
__device__ float g_Y2[(size_t)MAXN * 256];
// packed bf16 hi/lo planes (mma-ready: word w = bf16x2(v[2w], v[2w+1]))
__device__ uint32_t g_xHi[(size_t)NPAD * 128];
__device__ uint32_t g_xLo[(size_t)NPAD * 128];
__device__ uint32_t g_cHi[(size_t)NPAD * 64];
__device__ uint32_t g_cLo[(size_t)NPAD * 64];
__device__ uint32_t g_AeHi[(size_t)NPAD * 64];
__device__ uint32_t g_AeLo[(size_t)NPAD * 64];
__device__ uint32_t g_AcHi[(size_t)NPAD * 64];
__device__ uint32_t g_AcLo[(size_t)NPAD * 64];
__device__ int g_cnt[MAXN];
__device__ int g_fill[MAXN];
__device__ int g_rowptr[MAXN + 1];
__device__ int g_csrc[MAXE];

__device__ __forceinline__ float lrelu(float v) { return v > 0.f ? v : 0.2f * v; }

// split two floats into bf16x2 hi word + bf16x2 lo word
__device__ __forceinline__ void split2(float x, float y, uint32_t& hi, uint32_t& lo) {
    __nv_bfloat162 h = __float22bfloat162_rn(make_float2(x, y));
    hi = *reinterpret_cast<uint32_t*>(&h);
    float rx = x - __bfloat162float(h.x);
    float ry = y - __bfloat162float(h.y);
    __nv_bfloat162 l = __float22bfloat162_rn(make_float2(rx, ry));
    lo = *reinterpret_cast<uint32_t*>(&l);
}

// ---------------- input pre-pack (me-substitution fused) ----------------
// A: [M, K] fp32 -> hi/lo planes [row][K/2 words]
__global__ void pack_kernel(const float* __restrict__ A, const float* __restrict__ me,
                            uint32_t* __restrict__ hiP, uint32_t* __restrict__ loP,
                            int M, int K)
{
    int Kq = K >> 2;
    int idx = blockIdx.x * blockDim.x + threadIdx.x;
    if (idx >= M * Kq) return;
    int row = idx / Kq;
    int q4 = (idx - row * Kq) << 2;
    float4 v = *(const float4*)(A + (size_t)row * K + q4);
    if (v.x == 0.f) v.x = me[q4 + 0];
    if (v.y == 0.f) v.y = me[q4 + 1];
    if (v.z == 0.f) v.z = me[q4 + 2];
    if (v.w == 0.f) v.w = me[q4 + 3];
    uint32_t h0, l0, h1, l1;
    split2(v.x, v.y, h0, l0);
    split2(v.z, v.w, h1, l1);
    size_t off = (size_t)row * (K >> 1) + (q4 >> 1);
    *(uint2*)(hiP + off) = make_uint2(h0, h1);
    *(uint2*)(loP + off) = make_uint2(l0, l1);
}

// ---------------- CSR build ----------------
__global__ void zero_cnt_kernel(int n) {
    int i = blockIdx.x * blockDim.x + threadIdx.x;
    if (i < n) g_cnt[i] = 0;
}

__global__ void hist_kernel(const int* __restrict__ ei, int E) {
    int e = blockIdx.x * blockDim.x + threadIdx.x;
    if (e < E) atomicAdd(&g_cnt[ei[E + e]], 1);
}

__global__ __launch_bounds__(1024) void scan_kernel(int N) {
    __shared__ int ssum[1024];
    int tid = threadIdx.x;
    int chunk = (N + 1023) / 1024;
    int lo = tid * chunk;
    int hi = lo + chunk;
    if (hi > N) hi = N;
    int s = 0;
    for (int i = lo; i < hi; i++) s += g_cnt[i];
    ssum[tid] = s;
    __syncthreads();
    for (int off = 1; off < 1024; off <<= 1) {
        int t = (tid >= off) ? ssum[tid - off] : 0;
        __syncthreads();
        ssum[tid] += t;
        __syncthreads();
    }
    int run = ssum[tid] - s;
    for (int i = lo; i < hi; i++) {
        g_rowptr[i] = run;
        g_fill[i] = run;
        run += g_cnt[i];
    }
    if (tid == 1023) g_rowptr[N] = ssum[1023];
}

__global__ void fill_kernel(const int* __restrict__ ei, int E) {
    int e = blockIdx.x * blockDim.x + threadIdx.x;
    if (e < E) {
        int s = ei[e];
        int d = ei[E + e];
        int pos = atomicAdd(&g_fill[d], 1);
        g_csrc[pos] = s;
    }
}

#define MMA_BF16(D, Areg, B0, B1)                                            \
    asm volatile("mma.sync.aligned.m16n8k16.row.col.f32.bf16.bf16.f32 "      \
                 "{%0,%1,%2,%3},{%4,%5,%6,%7},{%8,%9},{%0,%1,%2,%3};"        \
                 : "+f"(D[0]), "+f"(D[1]), "+f"(D[2]), "+f"(D[3])            \
                 : "r"(Areg[0]), "r"(Areg[1]), "r"(Areg[2]), "r"(Areg[3]),   \
                   "r"(B0), "r"(B1))

// ---------------- Unified packed-A BF16x3 GEMM (cp.async A pipeline, per-chunk B split) ----------------
// A: packed hi/lo planes [rows][ldw words]; B: fp32 [K,128] row-major;
// Y: fp32 out, +col offset folded, row stride 256.
__global__ __launch_bounds__(256, 2) void gemm_packed_kernel(
    const uint32_t* __restrict__ aHi, const uint32_t* __restrict__ aLo, int ldw,
    const float* __restrict__ B, float* __restrict__ Y, int M, int K)
{
    __shared__ uint32_t sAhi[2][128][12], sAlo[2][128][12];
    __shared__ uint32_t Bhi[8][132], Blo[8][132];

    const int tid = threadIdx.x;
    const int lane = tid & 31;
    const int warp = tid >> 5;
    const int wr = warp & 1;
    const int wc = warp >> 1;
    const int rowBase = blockIdx.x * 128;
    const int nC = K >> 4;

    float d[4][4][4];
#pragma unroll
    for (int m = 0; m < 4; m++)
#pragma unroll
        for (int n = 0; n < 4; n++)
#pragma unroll
            for (int r = 0; r < 4; r++) d[m][n][r] = 0.f;

    const int c_row = tid >> 1;
    const int c_half = tid & 1;
    const uint32_t* srcHi = aHi + (size_t)(rowBase + c_row) * ldw + c_half * 4;
    const uint32_t* srcLo = aLo + (size_t)(rowBase + c_row) * ldw + c_half * 4;

    auto issueA = [&](int chunk) {
        int stage = chunk & 1;
        uint32_t dh = (uint32_t)__cvta_generic_to_shared(&sAhi[stage][c_row][c_half * 4]);
        uint32_t dl = (uint32_t)__cvta_generic_to_shared(&sAlo[stage][c_row][c_half * 4]);
        asm volatile("cp.async.cg.shared.global [%0], [%1], 16;" :: "r"(dh), "l"(srcHi + chunk * 8));
        asm volatile("cp.async.cg.shared.global [%0], [%1], 16;" :: "r"(dl), "l"(srcLo + chunk * 8));
        asm volatile("cp.async.commit_group;");
    };

    const int b_kp = tid >> 5;
    const int b_c4 = lane << 2;
    float4 pbe, pbo;

    auto prefetchB = [&](int k0) {
        pbe = *(const float4*)(B + (size_t)(k0 + 2 * b_kp) * 128 + b_c4);
        pbo = *(const float4*)(B + (size_t)(k0 + 2 * b_kp + 1) * 128 + b_c4);
    };

    auto storeB = [&]() {
        float ev[4] = {pbe.x, pbe.y, pbe.z, pbe.w};
        float od[4] = {pbo.x, pbo.y, pbo.z, pbo.w};
#pragma unroll
        for (int i = 0; i < 4; i++) {
            uint32_t h, l;
            split2(ev[i], od[i], h, l);
            Bhi[b_kp][b_c4 + i] = h;
            Blo[b_kp][b_c4 + i] = l;
        }
    };

    issueA(0);
    if (nC > 1) issueA(1);
    prefetchB(0);

    const int kp = lane & 3;
#pragma unroll 1
    for (int chunk = 0; chunk < nC; chunk++) {
        storeB();
        if (chunk < nC - 2) asm volatile("cp.async.wait_group 1;");
        else                asm volatile("cp.async.wait_group 0;");
        __syncthreads();
        if (chunk + 1 < nC) prefetchB((chunk + 1) * 16);

        const uint32_t (*Ah)[12] = sAhi[chunk & 1];
        const uint32_t (*Al)[12] = sAlo[chunk & 1];

        uint32_t ah[4][4], al[4][4];
#pragma unroll
        for (int m = 0; m < 4; m++) {
            int r0 = wr * 64 + m * 16 + (lane >> 2);
            ah[m][0] = Ah[r0][kp];
            ah[m][1] = Ah[r0 + 8][kp];
            ah[m][2] = Ah[r0][kp + 4];
            ah[m][3] = Ah[r0 + 8][kp + 4];
            al[m][0] = Al[r0][kp];
            al[m][1] = Al[r0 + 8][kp];
            al[m][2] = Al[r0][kp + 4];
            al[m][3] = Al[r0 + 8][kp + 4];
        }
#pragma unroll
        for (int n = 0; n < 4; n++) {
            int cb = wc * 32 + n * 8 + (lane >> 2);
            uint32_t bh0 = Bhi[kp][cb], bh1 = Bhi[kp + 4][cb];
            uint32_t bl0 = Blo[kp][cb], bl1 = Blo[kp + 4][cb];
#pragma unroll
            for (int m = 0; m < 4; m++) {
                MMA_BF16(d[m][n], ah[m], bh0, bh1);
                MMA_BF16(d[m][n], al[m], bh0, bh1);
                MMA_BF16(d[m][n], ah[m], bl0, bl1);
            }
        }
        __syncthreads();
        if (chunk + 2 < nC) issueA(chunk + 2);
    }

#pragma unroll
    for (int m = 0; m < 4; m++) {
        int r = rowBase + wr * 64 + m * 16 + (lane >> 2);
#pragma unroll
        for (int n = 0; n < 4; n++) {
            int cc = wc * 32 + n * 8 + ((lane & 3) << 1);
            if (r < M)
                *(float2*)(Y + (size_t)r * 256 + cc) = make_float2(d[m][n][0], d[m][n][1]);
            if (r + 8 < M)
                *(float2*)(Y + (size_t)(r + 8) * 256 + cc) = make_float2(d[m][n][2], d[m][n][3]);
        }
    }
}

// ---------------- gather core (warp-per-node neighbor sum) ----------------
__device__ __forceinline__ void gather_row(const float* __restrict__ Y, int gwarp,
                                           int lane, int j0, float* acc)
{
    const unsigned FULL = 0xffffffffu;
    int beg = g_rowptr[gwarp];
    int end = g_rowptr[gwarp + 1];
#pragma unroll
    for (int i = 0; i < 8; i++) acc[i] = 0.f;

    for (int base = beg; base < end; base += 32) {
        int idx = base + lane;
        int sl = (idx < end) ? g_csrc[idx] : 0;
        int cnt = end - base;
        if (cnt > 32) cnt = 32;
        int j = 0;
        for (; j + 3 < cnt; j += 4) {
            int s0 = __shfl_sync(FULL, sl, j);
            int s1 = __shfl_sync(FULL, sl, j + 1);
            int s2 = __shfl_sync(FULL, sl, j + 2);
            int s3 = __shfl_sync(FULL, sl, j + 3);
            const float* p0 = Y + (size_t)s0 * 256 + j0;
            const float* p1 = Y + (size_t)s1 * 256 + j0;
            const float* p2 = Y + (size_t)s2 * 256 + j0;
            const float* p3 = Y + (size_t)s3 * 256 + j0;
            float4 a0 = *(const float4*)p0;
            float4 a1 = *(const float4*)(p0 + 4);
            float4 b0 = *(const float4*)p1;
            float4 b1 = *(const float4*)(p1 + 4);
            float4 c0 = *(const float4*)p2;
            float4 c1 = *(const float4*)(p2 + 4);
            float4 e0 = *(const float4*)p3;
            float4 e1 = *(const float4*)(p3 + 4);
            acc[0] += (a0.x + b0.x) + (c0.x + e0.x);
            acc[1] += (a0.y + b0.y) + (c0.y + e0.y);
            acc[2] += (a0.z + b0.z) + (c0.z + e0.z);
            acc[3] += (a0.w + b0.w) + (c0.w + e0.w);
            acc[4] += (a1.x + b1.x) + (c1.x + e1.x);
            acc[5] += (a1.y + b1.y) + (c1.y + e1.y);
            acc[6] += (a1.z + b1.z) + (c1.z + e1.z);
            acc[7] += (a1.w + b1.w) + (c1.w + e1.w);
        }
        for (; j < cnt; j++) {
            int s0 = __shfl_sync(FULL, sl, j);
            const float* p0 = Y + (size_t)s0 * 256 + j0;
            float4 a0 = *(const float4*)p0;
            float4 a1 = *(const float4*)(p0 + 4);
            acc[0] += a0.x; acc[1] += a0.y; acc[2] += a0.z; acc[3] += a0.w;
            acc[4] += a1.x; acc[5] += a1.y; acc[6] += a1.z; acc[7] += a1.w;
        }
    }
}

__device__ __forceinline__ void gin_epilogue(const float* __restrict__ Y, int gwarp, int j0,
                                             const float* bb, float fac,
                                             const float* acc, float* h)
{
    const float* py = Y + (size_t)gwarp * 256 + j0;
    float4 y0 = *(const float4*)py;
    float4 y1 = *(const float4*)(py + 4);
    h[0] = lrelu(fmaf(y0.x, fac, acc[0]) + bb[0]);
    h[1] = lrelu(fmaf(y0.y, fac, acc[1]) + bb[1]);
    h[2] = lrelu(fmaf(y0.z, fac, acc[2]) + bb[2]);
    h[3] = lrelu(fmaf(y0.w, fac, acc[3]) + bb[3]);
    h[4] = lrelu(fmaf(y1.x, fac, acc[4]) + bb[4]);
    h[5] = lrelu(fmaf(y1.y, fac, acc[5]) + bb[5]);
    h[6] = lrelu(fmaf(y1.z, fac, acc[6]) + bb[6]);
    h[7] = lrelu(fmaf(y1.w, fac, acc[7]) + bb[7]);
}

// gather-1: writes packed bf16 hi/lo planes (mma-ready for layer-2 GEMM)
__global__ __launch_bounds__(256) void gather1_kernel(
    const float* __restrict__ Y,
    const float* __restrict__ be, const float* __restrict__ bc,
    const float* __restrict__ epe, const float* __restrict__ epc, int Nn)
{
    int gwarp = (blockIdx.x * 256 + threadIdx.x) >> 5;
    int lane = threadIdx.x & 31;
    if (gwarp >= Nn) return;
    int j0 = lane * 8;

    float acc[8];
    gather_row(Y, gwarp, lane, j0, acc);

    float fac;
    const float* bb;
    if (j0 < 128) { fac = 2.f + *epe; bb = be + j0; }
    else          { fac = 2.f + *epc; bb = bc + (j0 - 128); }

    float h[8];
    gin_epilogue(Y, gwarp, j0, bb, fac, acc, h);

    uint32_t hi[4], lo[4];
    split2(h[0], h[1], hi[0], lo[0]);
    split2(h[2], h[3], hi[1], lo[1]);
    split2(h[4], h[5], hi[2], lo[2]);
    split2(h[6], h[7], hi[3], lo[3]);

    if (lane < 16) {
        size_t off = (size_t)gwarp * 64 + lane * 4;
        *(uint4*)(g_AeHi + off) = make_uint4(hi[0], hi[1], hi[2], hi[3]);
        *(uint4*)(g_AeLo + off) = make_uint4(lo[0], lo[1], lo[2], lo[3]);
    } else {
        size_t off = (size_t)gwarp * 64 + (lane - 16) * 4;
        *(uint4*)(g_AcHi + off) = make_uint4(hi[0], hi[1], hi[2], hi[3]);
        *(uint4*)(g_AcLo + off) = make_uint4(lo[0], lo[1], lo[2], lo[3]);
    }
}

// gather-2: fused output head: out = lrelu(H2 @ Wm + bm)
__global__ __launch_bounds__(256) void gather2_kernel(
    const float* __restrict__ Y,
    const float* __restrict__ be, const float* __restrict__ bc,
    const float* __restrict__ epe, const float* __restrict__ epc,
    const float* __restrict__ Wm, const float* __restrict__ bm,
    float* __restrict__ out, int Nn)
{
    __shared__ float sW[2048];
    __shared__ float sb[8];
    for (int i = threadIdx.x; i < 2048; i += 256) sW[i] = Wm[i];
    if (threadIdx.x < 8) sb[threadIdx.x] = bm[threadIdx.x];
    __syncthreads();

    int gwarp = (blockIdx.x * 256 + threadIdx.x) >> 5;
    int lane = threadIdx.x & 31;
    if (gwarp >= Nn) return;
    int j0 = lane * 8;

    float acc[8];
    gather_row(Y, gwarp, lane, j0, acc);

    float fac;
    const float* bb;
    if (j0 < 128) { fac = 2.f + *epe; bb = be + j0; }
    else          { fac = 2.f + *epc; bb = bc + (j0 - 128); }

    float h[8];
    gin_epilogue(Y, gwarp, j0, bb, fac, acc, h);

    float o[8];
#pragma unroll
    for (int n = 0; n < 8; n++) o[n] = 0.f;
#pragma unroll
    for (int jj = 0; jj < 8; jj++) {
        const float* w = &sW[(size_t)(j0 + jj) * 8];
#pragma unroll
        for (int n = 0; n < 8; n++) o[n] += h[jj] * w[n];
    }
#pragma unroll
    for (int off = 16; off >= 1; off >>= 1)
#pragma unroll
        for (int n = 0; n < 8; n++)
            o[n] += __shfl_xor_sync(0xffffffffu, o[n], off);
    if (lane == 0) {
#pragma unroll
        for (int n = 0; n < 8; n++)
            out[(size_t)gwarp * 8 + n] = lrelu(o[n] + sb[n]);
    }
}

// ---------------- central MLP ----------------
__global__ __launch_bounds__(256) void central_kernel(
    const float* __restrict__ out, const int* __restrict__ cidx,
    const float* __restrict__ Wp1, const float* __restrict__ bp1,
    const float* __restrict__ Wp2, const float* __restrict__ bp2,
    float* __restrict__ logits, int C)
{
    __shared__ float s1[1024];
    __shared__ float sb1[128];
    __shared__ float s2[1024];
    __shared__ float sb2[8];
    for (int i = threadIdx.x; i < 1024; i += 256) { s1[i] = Wp1[i]; s2[i] = Wp2[i]; }
    if (threadIdx.x < 128) sb1[threadIdx.x] = bp1[threadIdx.x];
    if (threadIdx.x < 8) sb2[threadIdx.x] = bp2[threadIdx.x];
    __syncthreads();

    int t = blockIdx.x * 256 + threadIdx.x;
    if (t >= C) return;
    int ci = cidx[t];
    float g[8];
#pragma unroll
    for (int k = 0; k < 8; k++) g[k] = out[(size_t)ci * 8 + k];
    float acc[8];
#pragma unroll
    for (int m = 0; m < 8; m++) acc[m] = sb2[m];
    for (int n = 0; n < 128; n++) {
        float tn = sb1[n];
#pragma unroll
        for (int k = 0; k < 8; k++) tn += g[k] * s1[k * 128 + n];
        tn = fmaxf(tn, 0.f);
#pragma unroll
        for (int m = 0; m < 8; m++) acc[m] += tn * s2[n * 8 + m];
    }
#pragma unroll
    for (int m = 0; m < 8; m++) logits[(size_t)t * 8 + m] = acc[m];
}

extern "C" void kernel_launch(void* const* d_in, const int* in_sizes, int n_in,
                              void* d_out, int out_size)
{
    const float* x    = (const float*)d_in[0];
    const float* c    = (const float*)d_in[1];
    const int*   ei   = (const int*)d_in[2];
    const int*   cidx = (const int*)d_in[3];
    const float* me_x = (const float*)d_in[4];
    const float* me_c = (const float*)d_in[5];
    const float* W1e  = (const float*)d_in[6];
    const float* b1e  = (const float*)d_in[7];
    const float* e1e  = (const float*)d_in[8];
    const float* W2e  = (const float*)d_in[9];
    const float* b2e  = (const float*)d_in[10];
    const float* e2e  = (const float*)d_in[11];
    const float* W1c  = (const float*)d_in[12];
    const float* b1c  = (const float*)d_in[13];
    const float* e1c  = (const float*)d_in[14];
    const float* W2c  = (const float*)d_in[15];
    const float* b2c  = (const float*)d_in[16];
    const float* e2c  = (const float*)d_in[17];
    const float* Wm   = (const float*)d_in[18];
    const float* bm   = (const float*)d_in[19];
    const float* Wp1  = (const float*)d_in[20];
    const float* bp1  = (const float*)d_in[21];
    const float* Wp2  = (const float*)d_in[22];
    const float* bp2  = (const float*)d_in[23];

    const int Nn = in_sizes[0] / NFE;       // 50000
    const int E  = in_sizes[2] / 2;         // 800000
    const int C  = in_sizes[3];             // 512

    float *Y1, *Y2;
    uint32_t *xHi, *xLo, *cHi, *cLo, *AeHi, *AeLo, *AcHi, *AcLo;
    cudaGetSymbolAddress((void**)&Y1, g_Y1);
    cudaGetSymbolAddress((void**)&Y2, g_Y2);
    cudaGetSymbolAddress((void**)&xHi, g_xHi);
    cudaGetSymbolAddress((void**)&xLo, g_xLo);
    cudaGetSymbolAddress((void**)&cHi, g_cHi);
    cudaGetSymbolAddress((void**)&cLo, g_cLo);
    cudaGetSymbolAddress((void**)&AeHi, g_AeHi);
    cudaGetSymbolAddress((void**)&AeLo, g_AeLo);
    cudaGetSymbolAddress((void**)&AcHi, g_AcHi);
    cudaGetSymbolAddress((void**)&AcLo, g_AcLo);

    float* out_p    = (float*)d_out;              // [N, 8]
    float* logits_p = (float*)d_out + (size_t)Nn * 8;

    // Fork-join stream overlap (R11 shape — single fork-join only).
    // Stream/events created fresh each call and intentionally not destroyed
    // (destroy during capture would break the graph).
    cudaStream_t s1;
    cudaEvent_t evFork, evJoin;
    cudaStreamCreateWithFlags(&s1, cudaStreamNonBlocking);
    cudaEventCreateWithFlags(&evFork, cudaEventDisableTiming);
    cudaEventCreateWithFlags(&evJoin, cudaEventDisableTiming);

    cudaEventRecord(evFork, 0);
    cudaStreamWaitEvent(s1, evFork, 0);

    // CSR build (by dst) on s1 — hidden under pack + layer-1 GEMMs
    zero_cnt_kernel<<<(Nn + 255) / 256, 256, 0, s1>>>(Nn);
    hist_kernel<<<(E + 255) / 256, 256, 0, s1>>>(ei, E);
    scan_kernel<<<1, 1024, 0, s1>>>(Nn);
    fill_kernel<<<(E + 255) / 256, 256, 0, s1>>>(ei, E);
    cudaEventRecord(evJoin, s1);

    int gridM = (Nn + 127) / 128;
    int gridW = (Nn * 32 + 255) / 256;

    // pre-pack inputs into bf16 hi/lo planes (me-substitution fused)
    {
        int tx = Nn * (NFE / 4);
        pack_kernel<<<(tx + 255) / 256, 256>>>(x, me_x, xHi, xLo, Nn, NFE);
        int tc = Nn * (NFC / 4);
        pack_kernel<<<(tc + 255) / 256, 256>>>(c, me_c, cHi, cLo, Nn, NFC);
    }

    // layer-1 projections (packed A, cp.async pipeline)
    gemm_packed_kernel<<<gridM, 256>>>(xHi, xLo, 128, W1e, Y1, Nn, NFE);
    gemm_packed_kernel<<<gridM, 256>>>(cHi, cLo, 64, W1c, Y1 + 128, Nn, NFC);

    // Join: gather1 needs both CSR and Y1
    cudaStreamWaitEvent(0, evJoin, 0);

    // layer-1 aggregation + epilogue -> packed H1
    gather1_kernel<<<gridW, 256>>>(Y1, b1e, b1c, e1e, e1c, Nn);

    // layer-2 projections (packed A, sequential on main stream)
    gemm_packed_kernel<<<gridM, 256>>>(AeHi, AeLo, 64, W2e, Y2, Nn, 128);
    gemm_packed_kernel<<<gridM, 256>>>(AcHi, AcLo, 64, W2c, Y2 + 128, Nn, 128);

    // layer-2 aggregation + fused output head
    gather2_kernel<<<gridW, 256>>>(Y2, b2e, b2c, e2e, e2c, Wm, bm, out_p, Nn);

    // central MLP
    central_kernel<<<(C + 255) / 256, 256>>>(out_p, cidx, Wp1, bp1, Wp2, bp2, logits_p, C);
}